// round 3
// baseline (speedup 1.0000x reference)
#include <cuda_runtime.h>
#include <cuda_bf16.h>
#include <math.h>

// ---------------------------------------------------------------------------
// SearchNet: cosine similarity top-k
//   query [512] f32, database [N,512] f32 (N=500000), top_num=100
//   out: [values(K) | indices-as-float(K)] where K = out_size/2
//
// Pipeline (5 kernels):
//   init    : zero hist/counters + normalize query
//   sims    : fused dot+norm, writes sortable keys AND level-1 histogram
//   scan    : parallel suffix-scan over 2048 bins -> threshold bin g_sel1
//   collect : gather all candidates with top-11-bit bin >= g_sel1
//   final   : exact rank among candidates (shared-mem staged), write top-K
// ---------------------------------------------------------------------------

#define D 512
#define MAXN (1 << 20)        // >= 500000
#define CAND_CAP 16384
#define SH_CAP 6144           // candidates staged in shared memory (48KB)

__device__ unsigned int g_keys[MAXN];
__device__ float        g_qn[D];
__device__ unsigned int g_hist1[2048];
__device__ unsigned int g_sel1;
__device__ unsigned int g_ncand;
__device__ unsigned int g_cand_key[CAND_CAP];
__device__ unsigned int g_cand_idx[CAND_CAP];

// float -> order-preserving uint
__device__ __forceinline__ unsigned int f2key(float f) {
    unsigned int u = __float_as_uint(f);
    return (u & 0x80000000u) ? ~u : (u | 0x80000000u);
}
__device__ __forceinline__ float key2f(unsigned int k) {
    unsigned int u = (k & 0x80000000u) ? (k ^ 0x80000000u) : ~k;
    return __uint_as_float(u);
}

// ---------------- init: zero scratch + normalize query ---------------------
__global__ __launch_bounds__(1024) void init_kernel(const float* __restrict__ q) {
    __shared__ float sh[512];
    __shared__ float inv;
    int t = threadIdx.x;
    // zero histogram + counter
    g_hist1[t] = 0;
    g_hist1[t + 1024] = 0;
    if (t == 0) g_ncand = 0;
    // query normalization (threads 0..511)
    float v = 0.f;
    if (t < D) { v = q[t]; sh[t] = v * v; }
    __syncthreads();
    for (int s = D / 2; s > 0; s >>= 1) {
        if (t < s) sh[t] += sh[t + s];
        __syncthreads();
    }
    if (t == 0) inv = 1.0f / fmaxf(sqrtf(sh[0]), 1e-8f);
    __syncthreads();
    if (t < D) g_qn[t] = v * inv;
}

// ---------------- fused dot + row-norm + histogram, 2 rows per warp --------
__global__ __launch_bounds__(256) void sims_kernel(const float* __restrict__ db, int N) {
    int warp = (blockIdx.x * blockDim.x + threadIdx.x) >> 5;
    int lane = threadIdx.x & 31;
    int r0 = warp * 2;
    if (r0 >= N) return;
    bool has1 = (r0 + 1) < N;

    const float4* q4 = (const float4*)g_qn;
    float4 q0 = q4[lane];
    float4 q1 = q4[lane + 32];
    float4 q2 = q4[lane + 64];
    float4 q3 = q4[lane + 96];

    const float4* rowA = (const float4*)(db + (size_t)r0 * D);
    const float4* rowB = (const float4*)(db + (size_t)(r0 + (has1 ? 1 : 0)) * D);

    // front-batch 8 independent DRAM loads
    float4 a0 = rowA[lane];
    float4 a1 = rowA[lane + 32];
    float4 a2 = rowA[lane + 64];
    float4 a3 = rowA[lane + 96];
    float4 b0 = rowB[lane];
    float4 b1 = rowB[lane + 32];
    float4 b2 = rowB[lane + 64];
    float4 b3 = rowB[lane + 96];

    float dotA = a0.x*q0.x + a0.y*q0.y + a0.z*q0.z + a0.w*q0.w
               + a1.x*q1.x + a1.y*q1.y + a1.z*q1.z + a1.w*q1.w
               + a2.x*q2.x + a2.y*q2.y + a2.z*q2.z + a2.w*q2.w
               + a3.x*q3.x + a3.y*q3.y + a3.z*q3.z + a3.w*q3.w;
    float n2A  = a0.x*a0.x + a0.y*a0.y + a0.z*a0.z + a0.w*a0.w
               + a1.x*a1.x + a1.y*a1.y + a1.z*a1.z + a1.w*a1.w
               + a2.x*a2.x + a2.y*a2.y + a2.z*a2.z + a2.w*a2.w
               + a3.x*a3.x + a3.y*a3.y + a3.z*a3.z + a3.w*a3.w;
    float dotB = b0.x*q0.x + b0.y*q0.y + b0.z*q0.z + b0.w*q0.w
               + b1.x*q1.x + b1.y*q1.y + b1.z*q1.z + b1.w*q1.w
               + b2.x*q2.x + b2.y*q2.y + b2.z*q2.z + b2.w*q2.w
               + b3.x*q3.x + b3.y*q3.y + b3.z*q3.z + b3.w*q3.w;
    float n2B  = b0.x*b0.x + b0.y*b0.y + b0.z*b0.z + b0.w*b0.w
               + b1.x*b1.x + b1.y*b1.y + b1.z*b1.z + b1.w*b1.w
               + b2.x*b2.x + b2.y*b2.y + b2.z*b2.z + b2.w*b2.w
               + b3.x*b3.x + b3.y*b3.y + b3.z*b3.z + b3.w*b3.w;

#pragma unroll
    for (int off = 16; off; off >>= 1) {
        dotA += __shfl_down_sync(0xFFFFFFFFu, dotA, off);
        n2A  += __shfl_down_sync(0xFFFFFFFFu, n2A, off);
        dotB += __shfl_down_sync(0xFFFFFFFFu, dotB, off);
        n2B  += __shfl_down_sync(0xFFFFFFFFu, n2B, off);
    }
    if (lane == 0) {
        unsigned int kA = f2key(dotA / fmaxf(sqrtf(n2A), 1e-8f));
        g_keys[r0] = kA;
        atomicAdd(&g_hist1[kA >> 21], 1u);
        if (has1) {
            unsigned int kB = f2key(dotB / fmaxf(sqrtf(n2B), 1e-8f));
            g_keys[r0 + 1] = kB;
            atomicAdd(&g_hist1[kB >> 21], 1u);
        }
    }
}

// ---------------- parallel suffix-scan: find threshold bin -----------------
__global__ __launch_bounds__(1024) void scan_kernel(int K) {
    __shared__ unsigned int bufA[2048], bufB[2048];
    int t = threadIdx.x;
    // reversed load: prefix over descending bins == suffix sum
    bufA[t]        = g_hist1[2047 - t];
    bufA[t + 1024] = g_hist1[1023 - t];
    __syncthreads();
    unsigned int* src = bufA;
    unsigned int* dst = bufB;
#pragma unroll
    for (int off = 1; off < 2048; off <<= 1) {
        for (int i = t; i < 2048; i += 1024) {
            unsigned int v = src[i];
            if (i >= off) v += src[i - off];
            dst[i] = v;
        }
        __syncthreads();
        unsigned int* tmp = src; src = dst; dst = tmp;
    }
    unsigned int need = (unsigned int)K;
    for (int i = t; i < 2048; i += 1024) {
        unsigned int S = src[i];
        unsigned int Sab = (i == 0) ? 0u : src[i - 1];
        if (S >= need && Sab < need) g_sel1 = (unsigned int)(2047 - i);
    }
}

// ---------------- collect candidates with top-11-bit bin >= threshold ------
__global__ __launch_bounds__(256) void collect_kernel(int N) {
    unsigned int sel = g_sel1;
    int n4 = N >> 2;
    const uint4* k4 = (const uint4*)g_keys;
    for (int i = blockIdx.x * blockDim.x + threadIdx.x; i < n4;
         i += gridDim.x * blockDim.x) {
        uint4 k = k4[i];
        int base = i << 2;
        if ((k.x >> 21) >= sel) {
            unsigned int p = atomicAdd(&g_ncand, 1u);
            if (p < CAND_CAP) { g_cand_key[p] = k.x; g_cand_idx[p] = base; }
        }
        if ((k.y >> 21) >= sel) {
            unsigned int p = atomicAdd(&g_ncand, 1u);
            if (p < CAND_CAP) { g_cand_key[p] = k.y; g_cand_idx[p] = base + 1; }
        }
        if ((k.z >> 21) >= sel) {
            unsigned int p = atomicAdd(&g_ncand, 1u);
            if (p < CAND_CAP) { g_cand_key[p] = k.z; g_cand_idx[p] = base + 2; }
        }
        if ((k.w >> 21) >= sel) {
            unsigned int p = atomicAdd(&g_ncand, 1u);
            if (p < CAND_CAP) { g_cand_key[p] = k.w; g_cand_idx[p] = base + 3; }
        }
    }
    if (blockIdx.x == 0) {
        for (int i = (n4 << 2) + threadIdx.x; i < N; i += blockDim.x) {
            unsigned int key = g_keys[i];
            if ((key >> 21) >= sel) {
                unsigned int p = atomicAdd(&g_ncand, 1u);
                if (p < CAND_CAP) { g_cand_key[p] = key; g_cand_idx[p] = (unsigned int)i; }
            }
        }
    }
}

// ---------------- rank candidates, write top-K (jax tie-break: lower idx) --
__global__ __launch_bounds__(1024) void final_kernel(float* __restrict__ out, int K) {
    __shared__ unsigned int sk[SH_CAP];
    __shared__ unsigned int si[SH_CAP];
    unsigned int n = g_ncand;
    if (n > CAND_CAP) n = CAND_CAP;
    bool use_sh = (n <= SH_CAP);
    if (use_sh) {
        for (unsigned int i = threadIdx.x; i < n; i += blockDim.x) {
            sk[i] = g_cand_key[i];
            si[i] = g_cand_idx[i];
        }
        __syncthreads();
    }
    for (unsigned int c = threadIdx.x; c < n; c += blockDim.x) {
        unsigned int key = use_sh ? sk[c] : g_cand_key[c];
        unsigned int idx = use_sh ? si[c] : g_cand_idx[c];
        unsigned int rank = 0;
        if (use_sh) {
            for (unsigned int j = 0; j < n; j++) {
                unsigned int kj = sk[j];
                if (kj > key || (kj == key && si[j] < idx)) rank++;
            }
        } else {
            for (unsigned int j = 0; j < n; j++) {
                unsigned int kj = g_cand_key[j];
                if (kj > key || (kj == key && g_cand_idx[j] < idx)) rank++;
            }
        }
        if (rank < (unsigned int)K) {
            out[rank]     = key2f(key);
            out[K + rank] = (float)idx;
        }
    }
}

// ---------------------------------------------------------------------------
extern "C" void kernel_launch(void* const* d_in, const int* in_sizes, int n_in,
                              void* d_out, int out_size) {
    const float* q  = (const float*)d_in[0];
    const float* db = (const float*)d_in[1];
    int N = in_sizes[1] / D;
    int K = out_size / 2;   // values + indices
    float* out = (float*)d_out;

    int g = (N / 4 + 255) / 256;
    if (g > 1024) g = 1024;
    int simsBlocks = (N + 15) / 16;   // 8 warps/block, 2 rows/warp

    init_kernel<<<1, 1024>>>(q);
    sims_kernel<<<simsBlocks, 256>>>(db, N);
    scan_kernel<<<1, 1024>>>(K);
    collect_kernel<<<g, 256>>>(N);
    final_kernel<<<1, 1024>>>(out, K);
}

// round 4
// speedup vs baseline: 2.6669x; 2.6669x over previous
#include <cuda_runtime.h>
#include <cuda_bf16.h>
#include <math.h>

// ---------------------------------------------------------------------------
// SearchNet: cosine similarity top-k
//   query [512] f32, database [N,512] f32 (N=500000), top_num=100
//   out: [values(K) | indices-as-float(K)] where K = out_size/2
//
// Pipeline (6 kernels):
//   init    : zero hist/counters + normalize query
//   sims    : fused dot+norm -> sortable keys (NO atomics: DRAM-bound pass)
//   hist    : level-1 histogram of top 11 key bits, smem-aggregated
//   scan    : parallel suffix-scan over 2048 bins -> threshold bin g_sel1
//   collect : gather all candidates with top-11-bit bin >= g_sel1
//   final   : exact rank among candidates (shared-mem staged), write top-K
// ---------------------------------------------------------------------------

#define D 512
#define MAXN (1 << 20)        // >= 500000
#define CAND_CAP 16384
#define SH_CAP 6144           // candidates staged in shared memory (48KB)

__device__ unsigned int g_keys[MAXN];
__device__ float        g_qn[D];
__device__ unsigned int g_hist1[2048];
__device__ unsigned int g_sel1;
__device__ unsigned int g_ncand;
__device__ unsigned int g_cand_key[CAND_CAP];
__device__ unsigned int g_cand_idx[CAND_CAP];

// float -> order-preserving uint
__device__ __forceinline__ unsigned int f2key(float f) {
    unsigned int u = __float_as_uint(f);
    return (u & 0x80000000u) ? ~u : (u | 0x80000000u);
}
__device__ __forceinline__ float key2f(unsigned int k) {
    unsigned int u = (k & 0x80000000u) ? (k ^ 0x80000000u) : ~k;
    return __uint_as_float(u);
}

// ---------------- init: zero scratch + normalize query ---------------------
__global__ __launch_bounds__(1024) void init_kernel(const float* __restrict__ q) {
    __shared__ float sh[512];
    __shared__ float inv;
    int t = threadIdx.x;
    g_hist1[t] = 0;
    g_hist1[t + 1024] = 0;
    if (t == 0) g_ncand = 0;
    float v = 0.f;
    if (t < D) { v = q[t]; sh[t] = v * v; }
    __syncthreads();
    for (int s = D / 2; s > 0; s >>= 1) {
        if (t < s) sh[t] += sh[t + s];
        __syncthreads();
    }
    if (t == 0) inv = 1.0f / fmaxf(sqrtf(sh[0]), 1e-8f);
    __syncthreads();
    if (t < D) g_qn[t] = v * inv;
}

// ---------------- fused dot + row-norm, 2 rows per warp, NO atomics --------
__global__ __launch_bounds__(256) void sims_kernel(const float* __restrict__ db, int N) {
    int warp = (blockIdx.x * blockDim.x + threadIdx.x) >> 5;
    int lane = threadIdx.x & 31;
    int r0 = warp * 2;
    if (r0 >= N) return;
    bool has1 = (r0 + 1) < N;

    const float4* q4 = (const float4*)g_qn;
    float4 q0 = q4[lane];
    float4 q1 = q4[lane + 32];
    float4 q2 = q4[lane + 64];
    float4 q3 = q4[lane + 96];

    const float4* rowA = (const float4*)(db + (size_t)r0 * D);
    const float4* rowB = (const float4*)(db + (size_t)(r0 + (has1 ? 1 : 0)) * D);

    // front-batch 8 independent DRAM loads
    float4 a0 = rowA[lane];
    float4 a1 = rowA[lane + 32];
    float4 a2 = rowA[lane + 64];
    float4 a3 = rowA[lane + 96];
    float4 b0 = rowB[lane];
    float4 b1 = rowB[lane + 32];
    float4 b2 = rowB[lane + 64];
    float4 b3 = rowB[lane + 96];

    float dotA = a0.x*q0.x + a0.y*q0.y + a0.z*q0.z + a0.w*q0.w
               + a1.x*q1.x + a1.y*q1.y + a1.z*q1.z + a1.w*q1.w
               + a2.x*q2.x + a2.y*q2.y + a2.z*q2.z + a2.w*q2.w
               + a3.x*q3.x + a3.y*q3.y + a3.z*q3.z + a3.w*q3.w;
    float n2A  = a0.x*a0.x + a0.y*a0.y + a0.z*a0.z + a0.w*a0.w
               + a1.x*a1.x + a1.y*a1.y + a1.z*a1.z + a1.w*a1.w
               + a2.x*a2.x + a2.y*a2.y + a2.z*a2.z + a2.w*a2.w
               + a3.x*a3.x + a3.y*a3.y + a3.z*a3.z + a3.w*a3.w;
    float dotB = b0.x*q0.x + b0.y*q0.y + b0.z*q0.z + b0.w*q0.w
               + b1.x*q1.x + b1.y*q1.y + b1.z*q1.z + b1.w*q1.w
               + b2.x*q2.x + b2.y*q2.y + b2.z*q2.z + b2.w*q2.w
               + b3.x*q3.x + b3.y*q3.y + b3.z*q3.z + b3.w*q3.w;
    float n2B  = b0.x*b0.x + b0.y*b0.y + b0.z*b0.z + b0.w*b0.w
               + b1.x*b1.x + b1.y*b1.y + b1.z*b1.z + b1.w*b1.w
               + b2.x*b2.x + b2.y*b2.y + b2.z*b2.z + b2.w*b2.w
               + b3.x*b3.x + b3.y*b3.y + b3.z*b3.z + b3.w*b3.w;

#pragma unroll
    for (int off = 16; off; off >>= 1) {
        dotA += __shfl_down_sync(0xFFFFFFFFu, dotA, off);
        n2A  += __shfl_down_sync(0xFFFFFFFFu, n2A, off);
        dotB += __shfl_down_sync(0xFFFFFFFFu, dotB, off);
        n2B  += __shfl_down_sync(0xFFFFFFFFu, n2B, off);
    }
    if (lane == 0) {
        g_keys[r0] = f2key(dotA / fmaxf(sqrtf(n2A), 1e-8f));
        if (has1) g_keys[r0 + 1] = f2key(dotB / fmaxf(sqrtf(n2B), 1e-8f));
    }
}

// ---------------- level-1 histogram: top 11 bits, smem-aggregated ----------
__global__ __launch_bounds__(256) void hist_kernel(int N) {
    __shared__ unsigned int sh[2048];
    for (int i = threadIdx.x; i < 2048; i += blockDim.x) sh[i] = 0;
    __syncthreads();
    int n4 = N >> 2;
    const uint4* k4 = (const uint4*)g_keys;
    for (int i = blockIdx.x * blockDim.x + threadIdx.x; i < n4;
         i += gridDim.x * blockDim.x) {
        uint4 k = k4[i];
        atomicAdd(&sh[k.x >> 21], 1u);
        atomicAdd(&sh[k.y >> 21], 1u);
        atomicAdd(&sh[k.z >> 21], 1u);
        atomicAdd(&sh[k.w >> 21], 1u);
    }
    if (blockIdx.x == 0) {
        for (int i = (n4 << 2) + threadIdx.x; i < N; i += blockDim.x)
            atomicAdd(&sh[g_keys[i] >> 21], 1u);
    }
    __syncthreads();
    for (int i = threadIdx.x; i < 2048; i += blockDim.x)
        if (sh[i]) atomicAdd(&g_hist1[i], sh[i]);
}

// ---------------- parallel suffix-scan: find threshold bin -----------------
__global__ __launch_bounds__(1024) void scan_kernel(int K) {
    __shared__ unsigned int bufA[2048], bufB[2048];
    int t = threadIdx.x;
    // reversed load: prefix over descending bins == suffix sum
    bufA[t]        = g_hist1[2047 - t];
    bufA[t + 1024] = g_hist1[1023 - t];
    __syncthreads();
    unsigned int* src = bufA;
    unsigned int* dst = bufB;
#pragma unroll
    for (int off = 1; off < 2048; off <<= 1) {
        for (int i = t; i < 2048; i += 1024) {
            unsigned int v = src[i];
            if (i >= off) v += src[i - off];
            dst[i] = v;
        }
        __syncthreads();
        unsigned int* tmp = src; src = dst; dst = tmp;
    }
    unsigned int need = (unsigned int)K;
    for (int i = t; i < 2048; i += 1024) {
        unsigned int S = src[i];
        unsigned int Sab = (i == 0) ? 0u : src[i - 1];
        if (S >= need && Sab < need) g_sel1 = (unsigned int)(2047 - i);
    }
}

// ---------------- collect candidates with top-11-bit bin >= threshold ------
__global__ __launch_bounds__(256) void collect_kernel(int N) {
    unsigned int sel = g_sel1;
    int n4 = N >> 2;
    const uint4* k4 = (const uint4*)g_keys;
    for (int i = blockIdx.x * blockDim.x + threadIdx.x; i < n4;
         i += gridDim.x * blockDim.x) {
        uint4 k = k4[i];
        int base = i << 2;
        if ((k.x >> 21) >= sel) {
            unsigned int p = atomicAdd(&g_ncand, 1u);
            if (p < CAND_CAP) { g_cand_key[p] = k.x; g_cand_idx[p] = base; }
        }
        if ((k.y >> 21) >= sel) {
            unsigned int p = atomicAdd(&g_ncand, 1u);
            if (p < CAND_CAP) { g_cand_key[p] = k.y; g_cand_idx[p] = base + 1; }
        }
        if ((k.z >> 21) >= sel) {
            unsigned int p = atomicAdd(&g_ncand, 1u);
            if (p < CAND_CAP) { g_cand_key[p] = k.z; g_cand_idx[p] = base + 2; }
        }
        if ((k.w >> 21) >= sel) {
            unsigned int p = atomicAdd(&g_ncand, 1u);
            if (p < CAND_CAP) { g_cand_key[p] = k.w; g_cand_idx[p] = base + 3; }
        }
    }
    if (blockIdx.x == 0) {
        for (int i = (n4 << 2) + threadIdx.x; i < N; i += blockDim.x) {
            unsigned int key = g_keys[i];
            if ((key >> 21) >= sel) {
                unsigned int p = atomicAdd(&g_ncand, 1u);
                if (p < CAND_CAP) { g_cand_key[p] = key; g_cand_idx[p] = (unsigned int)i; }
            }
        }
    }
}

// ---------------- rank candidates, write top-K (jax tie-break: lower idx) --
__global__ __launch_bounds__(1024) void final_kernel(float* __restrict__ out, int K) {
    __shared__ unsigned int sk[SH_CAP];
    __shared__ unsigned int si[SH_CAP];
    unsigned int n = g_ncand;
    if (n > CAND_CAP) n = CAND_CAP;
    bool use_sh = (n <= SH_CAP);
    if (use_sh) {
        for (unsigned int i = threadIdx.x; i < n; i += blockDim.x) {
            sk[i] = g_cand_key[i];
            si[i] = g_cand_idx[i];
        }
        __syncthreads();
    }
    for (unsigned int c = threadIdx.x; c < n; c += blockDim.x) {
        unsigned int key = use_sh ? sk[c] : g_cand_key[c];
        unsigned int idx = use_sh ? si[c] : g_cand_idx[c];
        unsigned int rank = 0;
        if (use_sh) {
            for (unsigned int j = 0; j < n; j++) {
                unsigned int kj = sk[j];
                if (kj > key || (kj == key && si[j] < idx)) rank++;
            }
        } else {
            for (unsigned int j = 0; j < n; j++) {
                unsigned int kj = g_cand_key[j];
                if (kj > key || (kj == key && g_cand_idx[j] < idx)) rank++;
            }
        }
        if (rank < (unsigned int)K) {
            out[rank]     = key2f(key);
            out[K + rank] = (float)idx;
        }
    }
}

// ---------------------------------------------------------------------------
extern "C" void kernel_launch(void* const* d_in, const int* in_sizes, int n_in,
                              void* d_out, int out_size) {
    const float* q  = (const float*)d_in[0];
    const float* db = (const float*)d_in[1];
    int N = in_sizes[1] / D;
    int K = out_size / 2;   // values + indices
    float* out = (float*)d_out;

    int g = (N / 4 + 255) / 256;
    if (g > 1024) g = 1024;
    int simsBlocks = (N + 15) / 16;   // 8 warps/block, 2 rows/warp

    init_kernel<<<1, 1024>>>(q);
    sims_kernel<<<simsBlocks, 256>>>(db, N);
    hist_kernel<<<g, 256>>>(N);
    scan_kernel<<<1, 1024>>>(K);
    collect_kernel<<<g, 256>>>(N);
    final_kernel<<<1, 1024>>>(out, K);
}